// round 14
// baseline (speedup 1.0000x reference)
#include <cuda_runtime.h>
#include <cuda_bf16.h>
#include <cstdint>

#define NLINES 12288       // 24 planes * 512 lines
#define LW 512
#define KS 121
#define PB 528             // B row pitch in bytes (256 bf16 + 16B pad)

// dynamic smem layout
#define SM_BH 0            // B_hi [64 n][256 k] bf16, pitch PB: 33792 B
#define SM_BL 33792        // B_lo: 33792 B
#define SM_TBH 67584       // u32[176] hi pair table T[i] = (w[i-16], w[i-15])
#define SM_TBL 68288       // u32[176] lo table
#define SM_SRED 68992      // float[128]
#define SM_TOTAL 69504     // 3 CTAs/SM = 208.5 KB

__device__ float g_tmp[NLINES * LW];

static __device__ __forceinline__ uint32_t s2u(const void* p) {
    uint32_t a;
    asm("{ .reg .u64 t; cvta.to.shared.u64 t, %1; cvt.u32.u64 %0, t; }" : "=r"(a) : "l"(p));
    return a;
}

static __device__ __forceinline__ void mma_bf16(float* c, uint32_t a0, uint32_t a1,
                                                uint32_t a2, uint32_t a3,
                                                uint32_t b0, uint32_t b1) {
    asm volatile(
        "mma.sync.aligned.m16n8k16.row.col.f32.bf16.bf16.f32 "
        "{%0,%1,%2,%3}, {%4,%5,%6,%7}, {%8,%9}, {%0,%1,%2,%3};"
        : "+f"(c[0]), "+f"(c[1]), "+f"(c[2]), "+f"(c[3])
        : "r"(a0), "r"(a1), "r"(a2), "r"(a3), "r"(b0), "r"(b1));
}

// one ldmatrix.x4: loads B fragments for j-tiles (2i, 2i+1), both k-halves
static __device__ __forceinline__ void ldm4(uint32_t& r0, uint32_t& r1,
                                            uint32_t& r2, uint32_t& r3, uint32_t adr) {
    asm volatile("ldmatrix.sync.aligned.m8n8.x4.shared.b16 {%0,%1,%2,%3}, [%4];"
                 : "=r"(r0), "=r"(r1), "=r"(r2), "=r"(r3) : "r"(adr));
}

static __device__ __forceinline__ uint32_t pack_bf2(float lo, float hi) {
    __nv_bfloat162 h;
    h.x = __float2bfloat16(lo);
    h.y = __float2bfloat16(hi);
    return *(uint32_t*)&h;
}

// ---------------------------------------------------------------------------
// One separable-blur pass as banded GEMM on tensor cores (mma.sync bf16,
// 3-term hi/lo error split, fp32 accum).  A[m,k] = w[k-m] Toeplitz band is
// generated from a 176-entry pair table (never materialized).  Per k-chunk,
// ALL 8 ldmatrix.x4 (hi AND lo, disjoint register sets) issue before the
// 40 MMAs -> deep LDSM pipelining, no WAR serialization.  Output written
// plane-transposed; two passes compose to the correct layout.
// ---------------------------------------------------------------------------
__global__ __launch_bounds__(256, 3)
void blur_pass(const float* __restrict__ x, float* __restrict__ outp,
               const float* __restrict__ sigma, int first) {
    extern __shared__ char smem[];
    uint32_t sbu = s2u(smem);
    int tid = threadIdx.x;
    int ib = blockIdx.x;             // 0..3: output block along the line
    int L0 = blockIdx.y * 64;        // first line of the 64-line tile

    const float* in = first ? x : (const float*)g_tmp;
    float* out = first ? (float*)g_tmp : outp;

    // ---- B build: thread = (k-pair k2 = tid&127, line-half = tid>>7) ----
    {
        int k2 = tid & 127, half = tid >> 7;
        int gx0 = min(max(ib * 128 - 60 + 2 * k2, 0), LW - 1);
        int gx1 = min(max(ib * 128 - 60 + 2 * k2 + 1, 0), LW - 1);
        const float* ip0 = in + (long)(L0 + half * 32) * LW + gx0;
        const float* ip1 = in + (long)(L0 + half * 32) * LW + gx1;
        char* bh = smem + SM_BH + half * 32 * PB + k2 * 4;
        char* bl = smem + SM_BL + half * 32 * PB + k2 * 4;
        #pragma unroll 4
        for (int n = 0; n < 32; n++) {
            float v0 = ip0[(long)n * LW];
            float v1 = ip1[(long)n * LW];
            float h0 = __bfloat162float(__float2bfloat16(v0));
            float h1 = __bfloat162float(__float2bfloat16(v1));
            *(uint32_t*)(bh + n * PB) = pack_bf2(v0, v1);
            *(uint32_t*)(bl + n * PB) = pack_bf2(v0 - h0, v1 - h1);
        }
    }

    // ---- weights + pair tables ----
    {
        float* sred = (float*)(smem + SM_SRED);
        float e = 0.0f;
        if (tid < 128) {
            float s = sigma[0] * 8.0f + 16.0f;
            float d = (float)(tid - 60);
            e = (tid < KS) ? expf(-(d * d) / (2.0f * s * s)) : 0.0f;
            sred[tid] = e;
        }
        __syncthreads();
        float* wf = (float*)(smem + SM_SRED);
        if (tid < 32) {
            float s4 = sred[tid] + sred[tid + 32] + sred[tid + 64] + sred[tid + 96];
            #pragma unroll
            for (int off = 16; off > 0; off >>= 1)
                s4 += __shfl_xor_sync(0xffffffffu, s4, off);
            if (tid == 0) sred[0] = s4;
        }
        __syncthreads();
        float sum = wf[0];
        __syncthreads();
        if (tid < 128) wf[tid] = e / sum;            // wf[121..127] = 0
        __syncthreads();
        if (tid < 176) {
            int i = tid - 16;
            float w0 = ((unsigned)i < 128u) ? wf[i] : 0.0f;
            float w1 = ((unsigned)(i + 1) < 128u) ? wf[i + 1] : 0.0f;
            float h0 = __bfloat162float(__float2bfloat16(w0));
            float h1 = __bfloat162float(__float2bfloat16(w1));
            ((uint32_t*)(smem + SM_TBH))[tid] = pack_bf2(w0, w1);
            ((uint32_t*)(smem + SM_TBL))[tid] = pack_bf2(w0 - h0, w1 - h1);
        }
    }
    __syncthreads();

    // ---- mainloop: warp = 16-row m-strip; 9 active k-chunks (band) ----
    int wid = tid >> 5, lane = tid & 31;
    int g = lane >> 2, t = lane & 3;
    int m0 = wid * 16;

    float c[8][4];
    #pragma unroll
    for (int j = 0; j < 8; j++)
        #pragma unroll
        for (int r = 0; r < 4; r++) c[j][r] = 0.0f;

    const uint32_t* tbh = (const uint32_t*)(smem + SM_TBH);
    const uint32_t* tbl = (const uint32_t*)(smem + SM_TBL);

    // ldmatrix lane address: matrix mi = lane>>3 -> (j_sub = mi>>1, khalf = mi&1),
    // row rr = lane&7.  addr(i,u) = A0h + i*16*PB + u*32.
    int mi = lane >> 3, rr = lane & 7;
    uint32_t A0h = sbu + SM_BH + (uint32_t)((8 * (mi >> 1) + rr) * PB)
                 + (uint32_t)(16 * (mi & 1)) + (uint32_t)(m0 * 2);
    uint32_t A0l = A0h + (SM_BL - SM_BH);
    int di0 = 2 * t - g + 16;

    #pragma unroll 1
    for (int u = 0; u < 9; u++) {
        // A-fragment table loads first (resolved before the MMA block)
        int idx = di0 + 16 * u;
        uint32_t ah0 = tbh[idx], ah1 = tbh[idx - 8], ah2 = tbh[idx + 8];
        uint32_t al0 = tbl[idx], al1 = tbl[idx - 8], al2 = tbl[idx + 8];

        // all 8 ldmatrix.x4 issued back-to-back into DISJOINT register sets
        uint32_t bh[8][2], bl[8][2];
        uint32_t ah = A0h + u * 32;
        uint32_t al = A0l + u * 32;
        ldm4(bh[0][0], bh[0][1], bh[1][0], bh[1][1], ah);
        ldm4(bh[2][0], bh[2][1], bh[3][0], bh[3][1], ah + 16 * PB);
        ldm4(bh[4][0], bh[4][1], bh[5][0], bh[5][1], ah + 32 * PB);
        ldm4(bh[6][0], bh[6][1], bh[7][0], bh[7][1], ah + 48 * PB);
        ldm4(bl[0][0], bl[0][1], bl[1][0], bl[1][1], al);
        ldm4(bl[2][0], bl[2][1], bl[3][0], bl[3][1], al + 16 * PB);
        ldm4(bl[4][0], bl[4][1], bl[5][0], bl[5][1], al + 32 * PB);
        ldm4(bl[6][0], bl[6][1], bl[7][0], bl[7][1], al + 48 * PB);

        #pragma unroll
        for (int j = 0; j < 8; j++)
            mma_bf16(c[j], ah0, ah1, ah2, ah0, bh[j][0], bh[j][1]);   // Ah*Bh
        #pragma unroll
        for (int j = 0; j < 8; j++)
            mma_bf16(c[j], al0, al1, al2, al0, bh[j][0], bh[j][1]);   // Al*Bh
        #pragma unroll
        for (int j = 0; j < 8; j++)
            mma_bf16(c[j], ah0, ah1, ah2, ah0, bl[j][0], bl[j][1]);   // Ah*Bl
    }

    // ---- epilogue: D[m][n] -> plane-transposed store ----
    {
        int p = L0 >> 9;                // plane
        int lp0 = L0 & 511;             // line within plane
        long row = (long)(p * 512 + ib * 128 + m0 + g);
        float* o0 = out + row * 512 + lp0;
        float* o1 = o0 + 8 * 512;       // row +8
        #pragma unroll
        for (int j = 0; j < 8; j++) {
            int n = 8 * j + 2 * t;
            *(float2*)(o0 + n) = make_float2(c[j][0], c[j][1]);
            *(float2*)(o1 + n) = make_float2(c[j][2], c[j][3]);
        }
    }
}

// ---------------------------------------------------------------------------
extern "C" void kernel_launch(void* const* d_in, const int* in_sizes, int n_in,
                              void* d_out, int out_size) {
    const float* x     = (const float*)d_in[0];
    const float* sigma = (const float*)d_in[1];
    float* out = (float*)d_out;

    cudaFuncSetAttribute(blur_pass, cudaFuncAttributeMaxDynamicSharedMemorySize,
                         SM_TOTAL);

    dim3 grid(LW / 128, NLINES / 64);   // 4 x 192 = 768 CTAs
    blur_pass<<<grid, 256, SM_TOTAL>>>(x, out, sigma, 1);   // x -> g_tmp (T)
    blur_pass<<<grid, 256, SM_TOTAL>>>(x, out, sigma, 0);   // g_tmp -> out (T back)
}

// round 15
// speedup vs baseline: 1.1782x; 1.1782x over previous
#include <cuda_runtime.h>
#include <cstdint>

#define NLINES 12288       // 24 planes * 512 lines
#define LW 512
#define KS 121
#define NT 32              // lines per CTA
#define PK 260             // B pitch in floats (260 mod 32 = 4 -> conflict-free frags)

// dynamic smem layout
#define SM_B 0             // B [32 n][256 k] fp32(tf32-rounded), pitch PK: 33280 B
#define SM_WT 33280        // u32[160] tf32 weight table wt[i] = w[i-16] (zeros outside)
#define SM_SRED 33920      // float[128]
#define SM_TOTAL 34432     // 6 CTAs/SM = 206.6 KB

__device__ float g_tmp[NLINES * LW];

static __device__ __forceinline__ uint32_t cvt_tf32(float v) {
    uint32_t o;
    asm("cvt.rna.tf32.f32 %0, %1;" : "=r"(o) : "f"(v));
    return o;
}

static __device__ __forceinline__ void mma_tf32(float* c, uint32_t a0, uint32_t a1,
                                                uint32_t a2, uint32_t a3,
                                                uint32_t b0, uint32_t b1) {
    asm volatile(
        "mma.sync.aligned.m16n8k8.row.col.f32.tf32.tf32.f32 "
        "{%0,%1,%2,%3}, {%4,%5,%6,%7}, {%8,%9}, {%0,%1,%2,%3};"
        : "+f"(c[0]), "+f"(c[1]), "+f"(c[2]), "+f"(c[3])
        : "r"(a0), "r"(a1), "r"(a2), "r"(a3), "r"(b0), "r"(b1));
}

// ---------------------------------------------------------------------------
// One separable-blur pass as banded GEMM on tensor cores, tf32 single-term.
// D[m=128, n=32] = A[m,k] B[n,k]^T with A[m,k] = w[k-m] Toeplitz (generated
// from a 160-entry scalar table, never materialized).  Inputs/weights rounded
// once to tf32; fp32 accumulate.  Output written plane-transposed; two passes
// compose to the correct layout.
// ---------------------------------------------------------------------------
__global__ __launch_bounds__(256, 6)
void blur_pass(const float* __restrict__ x, float* __restrict__ outp,
               const float* __restrict__ sigma, int first) {
    extern __shared__ char smem[];
    int tid = threadIdx.x;
    int ib = blockIdx.x;             // 0..3: 128-output block along the line
    int L0 = blockIdx.y * NT;        // first line of the 32-line tile

    const float* in = first ? x : (const float*)g_tmp;
    float* out = first ? (float*)g_tmp : outp;

    // ---- B build: thread owns k-column tid; 32 lines, tf32-rounded ----
    {
        int k = tid;
        int gx = min(max(ib * 128 - 60 + k, 0), LW - 1);
        const float* ip = in + (long)L0 * LW + gx;
        uint32_t* bsw = (uint32_t*)(smem + SM_B) + k;
        #pragma unroll 8
        for (int n = 0; n < NT; n++)
            bsw[n * PK] = cvt_tf32(ip[(long)n * LW]);
    }

    // ---- weight table: wt[i] = tf32(w[i-16]), zeros outside [16,136] ----
    {
        float* sred = (float*)(smem + SM_SRED);
        float e = 0.0f;
        if (tid < 128) {
            float s = sigma[0] * 8.0f + 16.0f;
            float d = (float)(tid - 60);
            e = (tid < KS) ? expf(-(d * d) / (2.0f * s * s)) : 0.0f;
            sred[tid] = e;
        }
        __syncthreads();
        if (tid < 32) {
            float s4 = sred[tid] + sred[tid + 32] + sred[tid + 64] + sred[tid + 96];
            #pragma unroll
            for (int off = 16; off > 0; off >>= 1)
                s4 += __shfl_xor_sync(0xffffffffu, s4, off);
            if (tid == 0) sred[0] = s4;
        }
        __syncthreads();
        float sum = sred[0];
        uint32_t* wtw = (uint32_t*)(smem + SM_WT);
        if (tid < 128)
            wtw[tid + 16] = cvt_tf32(e / sum);       // wt[16..143]; 137..143 are w=0
        if (tid < 16) wtw[tid] = 0u;                 // wt[0..15]
        if (tid >= 240) wtw[tid - 240 + 144] = 0u;   // wt[144..159]
    }
    __syncthreads();

    // ---- mainloop: warp = 16-row m-strip, 17 k8-chunks over the band ----
    int wid = tid >> 5, lane = tid & 31;
    int g = lane >> 2, t = lane & 3;
    int m0 = wid * 16;

    float c[4][4];
    #pragma unroll
    for (int j = 0; j < 4; j++)
        #pragma unroll
        for (int r = 0; r < 4; r++) c[j][r] = 0.0f;

    const uint32_t* wt = (const uint32_t*)(smem + SM_WT);
    const uint32_t* bs = (const uint32_t*)(smem + SM_B);

    #pragma unroll 1
    for (int u = 0; u < 17; u++) {
        int kb = m0 + 8 * u;
        int d0 = 8 * u + t - g;
        // A fragment (m16k8 tf32): a0(r=g,c=t) a1(r=g+8) a2(c=t+4) a3(both+)
        uint32_t a0 = wt[d0 + 16], a1 = wt[d0 + 8];
        uint32_t a2 = wt[d0 + 20], a3 = wt[d0 + 12];

        // B fragments (k8n8): b0 at (k=kb+t, n=8j+g), b1 at k+4
        uint32_t b[4][2];
        #pragma unroll
        for (int j = 0; j < 4; j++) {
            const uint32_t* bp = bs + (8 * j + g) * PK + kb + t;
            b[j][0] = bp[0];
            b[j][1] = bp[4];
        }
        #pragma unroll
        for (int j = 0; j < 4; j++)
            mma_tf32(c[j], a0, a1, a2, a3, b[j][0], b[j][1]);
    }

    // ---- epilogue: D[m][n] -> plane-transposed store ----
    {
        int p = L0 >> 9;                 // plane
        int lp0 = L0 & 511;              // line within plane
        long row = (long)(p * 512 + ib * 128 + m0 + g);
        float* o0 = out + row * 512 + lp0;
        float* o1 = o0 + 8 * 512;        // row +8
        #pragma unroll
        for (int j = 0; j < 4; j++) {
            int n = 8 * j + 2 * t;
            *(float2*)(o0 + n) = make_float2(c[j][0], c[j][1]);
            *(float2*)(o1 + n) = make_float2(c[j][2], c[j][3]);
        }
    }
}

// ---------------------------------------------------------------------------
extern "C" void kernel_launch(void* const* d_in, const int* in_sizes, int n_in,
                              void* d_out, int out_size) {
    const float* x     = (const float*)d_in[0];
    const float* sigma = (const float*)d_in[1];
    float* out = (float*)d_out;

    cudaFuncSetAttribute(blur_pass, cudaFuncAttributeMaxDynamicSharedMemorySize,
                         SM_TOTAL);

    dim3 grid(LW / 128, NLINES / NT);   // 4 x 384 = 1536 CTAs
    blur_pass<<<grid, 256, SM_TOTAL>>>(x, out, sigma, 1);   // x -> g_tmp (T)
    blur_pass<<<grid, 256, SM_TOTAL>>>(x, out, sigma, 0);   // g_tmp -> out (T back)
}